// round 9
// baseline (speedup 1.0000x reference)
#include <cuda_runtime.h>
#include <math.h>

#define N_IMG 16
#define HW 10000
#define HDIM 100

// ---------------- scratch (no allocations allowed) ----------------
__device__ float g_xc[10240000];       // (16,64,100,100)
__device__ float g_Gt[21233664];       // gathered U, channel-major [64][NC]
__device__ float g_A[21233664];        // window result, same layout
__device__ float g_mix[30720000];      // (16,192,100,100) folded concat
__device__ float g_meanU[147456];      // B*64
__device__ float g_z[147456];          // SE scales

// ---------------- big 1x1 conv: 64m x 256n tile, 8x8 thread tile ----------------
// Y[n,m,p] = sum_k W[m,k] * (X0[n,k,p] (+ X1[n,k,p])) + bias[m]
template<int KDIM, int MOUT, bool ADDX>
__global__ __launch_bounds__(256) void conv_big(
    const float* __restrict__ Wm, const float* __restrict__ bias,
    const float* __restrict__ X0, const float* __restrict__ X1,
    float* __restrict__ Y)
{
    extern __shared__ float sm[];
    float* Ws = sm;                  // [KDIM][68] transposed (k rows, m inner)
    float* Xs = sm + KDIM * 68;      // [16][264]
    const int tid = threadIdx.x;
    const int tx = tid & 31;         // n group (8 cols each)
    const int ty = tid >> 5;         // m group (8 rows each)
    const int p0 = blockIdx.x * 256;
    const int m0 = blockIdx.y * 64;
    const int n  = blockIdx.z;
    const float* Xb0 = X0 + (size_t)n * KDIM * HW;
    const float* Xb1 = X1 ? (X1 + (size_t)n * KDIM * HW) : (const float*)0;

    for (int idx = tid; idx < 64 * KDIM; idx += 256) {
        int mm = idx / KDIM;
        int kc = idx - mm * KDIM;
        Ws[kc * 68 + mm] = Wm[(m0 + mm) * KDIM + kc];
    }

    float acc[8][8];
#pragma unroll
    for (int i = 0; i < 8; i++)
#pragma unroll
        for (int j = 0; j < 8; j++) acc[i][j] = 0.f;

    for (int k0 = 0; k0 < KDIM; k0 += 16) {
        __syncthreads();
#pragma unroll
        for (int idx = tid; idx < 4096; idx += 256) {
            int kk = idx >> 8;
            int pp = idx & 255;
            int p = p0 + pp;
            float v = 0.f;
            if (p < HW) {
                v = Xb0[(size_t)(k0 + kk) * HW + p];
                if (ADDX) v += Xb1[(size_t)(k0 + kk) * HW + p];
            }
            Xs[kk * 264 + pp] = v;
        }
        __syncthreads();
#pragma unroll 8
        for (int kk = 0; kk < 16; kk++) {
            const float4 wa = *reinterpret_cast<const float4*>(Ws + (k0 + kk) * 68 + ty * 8);
            const float4 wb = *reinterpret_cast<const float4*>(Ws + (k0 + kk) * 68 + ty * 8 + 4);
            const float4 xa = *reinterpret_cast<const float4*>(Xs + kk * 264 + tx * 8);
            const float4 xb = *reinterpret_cast<const float4*>(Xs + kk * 264 + tx * 8 + 4);
            float wv[8] = {wa.x, wa.y, wa.z, wa.w, wb.x, wb.y, wb.z, wb.w};
            float xv[8] = {xa.x, xa.y, xa.z, xa.w, xb.x, xb.y, xb.z, xb.w};
#pragma unroll
            for (int i = 0; i < 8; i++)
#pragma unroll
                for (int j = 0; j < 8; j++)
                    acc[i][j] += wv[i] * xv[j];
        }
    }

    int p = p0 + tx * 8;
    if (p < HW) {                    // HW % 8 == 0, p multiple of 8 -> covers p..p+7
#pragma unroll
        for (int i = 0; i < 8; i++) {
            int m = m0 + ty * 8 + i;
            float bv = bias[m];
            float* yp = Y + (size_t)(n * MOUT + m) * HW + p;
            *reinterpret_cast<float4*>(yp) =
                make_float4(acc[i][0] + bv, acc[i][1] + bv, acc[i][2] + bv, acc[i][3] + bv);
            *reinterpret_cast<float4*>(yp + 4) =
                make_float4(acc[i][4] + bv, acc[i][5] + bv, acc[i][6] + bv, acc[i][7] + bv);
        }
    }
}

// ---------------- gather (channel-major) + per-(b,cp) mean ----------------
template<int NW, int K, int S>
__global__ __launch_bounds__(256) void gather_mean(
    const float* __restrict__ xc, float* __restrict__ Gt, float* __restrict__ meanU)
{
    constexpr int W2 = NW * NW;
    constexpr int KSQ = K * K;
    constexpr int M = 64 * KSQ;
    constexpr int NC = N_IMG * W2 * KSQ;
    const int b  = blockIdx.x >> 3;
    const int rb = blockIdx.x & 7;
    const int n = b / W2;
    const int q = b - n * W2;
    const float* xcn = xc + (size_t)n * 64 * HW;
    const int r = threadIdx.x >> 5;
    const int lane = threadIdx.x & 31;
    const int cp = rb * 8 + r;
    const int g0 = q * M + cp * KSQ;
    float s = 0.f;
    for (int sp = lane; sp < KSQ; sp += 32) {
        int g = g0 + sp;
        int m = g / W2;
        int w = g - m * W2;
        int cin = m / KSQ;
        int rem = m - cin * KSQ;
        int ki = rem / K, kj = rem - ki * K;
        int wi = w / NW, wj = w - wi * NW;
        float v = xcn[(cin * HDIM + wi * S + ki) * HDIM + wj * S + kj];
        Gt[(size_t)cp * NC + (size_t)b * KSQ + sp] = v;
        s += v;
    }
#pragma unroll
    for (int off = 16; off; off >>= 1) s += __shfl_down_sync(0xffffffffu, s, off);
    if (lane == 0) meanU[b * 64 + cp] = s * (1.0f / KSQ);
}

// ---------------- SE head (tiny) ----------------
__global__ void se_kernel(const float* __restrict__ meanU, const float* __restrict__ w2,
                          const float* __restrict__ b2, const float* __restrict__ wse1,
                          const float* __restrict__ wse2, float* __restrict__ z)
{
    __shared__ float mu[64], my[64], hb[4];
    int b = blockIdx.x, t = threadIdx.x;
    mu[t] = meanU[b * 64 + t];
    __syncthreads();
    float acc = b2[t];
#pragma unroll 8
    for (int c = 0; c < 64; c++) acc += w2[t * 64 + c] * mu[c];
    my[t] = acc;
    __syncthreads();
    if (t < 4) {
        float h = 0.f;
#pragma unroll 8
        for (int o = 0; o < 64; o++) h += wse1[t * 64 + o] * my[o];
        hb[t] = fmaxf(h, 0.f);
    }
    __syncthreads();
    float za = 0.f;
#pragma unroll
    for (int j = 0; j < 4; j++) za += wse2[t * 4 + j] * hb[j];
    z[b * 64 + t] = 1.f / (1.f + expf(-za));
}

// ---------------- fused window GEMM + dwconv epilogue ----------------
// A[o][col] = z[b][o]*( (w2@Gt)[o][col] + b2[o] ) + dwconv3x3(Gt)[o][col]
// 64m x 128n tile, thread 8m x 4n, whole-K (64) X tile resident with dwconv halo.
template<int K, int NC, int LPAD, int STRIDE>
__global__ __launch_bounds__(256) void wgemm_dw(
    const float* __restrict__ Wm, const float* __restrict__ b2,
    const float* __restrict__ Gt, const float* __restrict__ wpos,
    const float* __restrict__ bpos, const float* __restrict__ z,
    float* __restrict__ A)
{
    constexpr int KSQ = K * K;
    constexpr int SW = LPAD + 128 + K + 2;      // halo: [p0-LPAD, p0+128+K+1]
    extern __shared__ float sm[];
    float* Ws  = sm;                 // [64][68]
    float* Xs  = sm + 4352;          // [64][STRIDE]
    float* wps = Xs + 64 * STRIDE;   // 576
    float* b2s = wps + 576;          // 64
    float* bps = b2s + 64;           // 64
    const int tid = threadIdx.x;
    const int tx = tid & 31;
    const int ty = tid >> 5;
    const int p0 = blockIdx.x * 128;

    for (int idx = tid; idx < 4096; idx += 256) {
        int mm = idx >> 6;
        int kc = idx & 63;
        Ws[kc * 68 + mm] = Wm[mm * 64 + kc];
    }
    {
        const int base = p0 - LPAD;
        for (int idx = tid; idx < 64 * SW; idx += 256) {
            int r = idx / SW;
            int c = idx - r * SW;
            int g = base + c;
            Xs[r * STRIDE + c] = (g >= 0 && g < NC) ? Gt[(size_t)r * NC + g] : 0.f;
        }
    }
    for (int idx = tid; idx < 576; idx += 256) wps[idx] = wpos[idx];
    if (tid < 64) { b2s[tid] = b2[tid]; bps[tid] = bpos[tid]; }
    __syncthreads();

    float acc[8][4];
#pragma unroll
    for (int i = 0; i < 8; i++)
#pragma unroll
        for (int j = 0; j < 4; j++) acc[i][j] = 0.f;

#pragma unroll 8
    for (int kk = 0; kk < 64; kk++) {
        const float4 wa = *reinterpret_cast<const float4*>(Ws + kk * 68 + ty * 8);
        const float4 wb = *reinterpret_cast<const float4*>(Ws + kk * 68 + ty * 8 + 4);
        const float4 x4 = *reinterpret_cast<const float4*>(Xs + kk * STRIDE + LPAD + tx * 4);
        float wv[8] = {wa.x, wa.y, wa.z, wa.w, wb.x, wb.y, wb.z, wb.w};
        float xv[4] = {x4.x, x4.y, x4.z, x4.w};
#pragma unroll
        for (int i = 0; i < 8; i++)
#pragma unroll
            for (int j = 0; j < 4; j++)
                acc[i][j] += wv[i] * xv[j];
    }

    // epilogue: SE scale + bias + dwconv from resident Xs (masked neighbors)
    const int j0 = p0 + tx * 4;      // NC % 128 == 0 -> always in range
#pragma unroll
    for (int jj = 0; jj < 4; jj++) {
        int col = j0 + jj;
        int bp = col / KSQ;
        int sp = col - bp * KSQ;
        int si = sp / K;
        int sj = sp - si * K;
        bool mu_ = (si > 0), md = (si < K - 1);
        bool ml = (sj > 0), mr = (sj < K - 1);
#pragma unroll
        for (int i = 0; i < 8; i++) {
            int o = ty * 8 + i;
            const float* xr = Xs + o * STRIDE + LPAD + tx * 4 + jj;
            const float* wp = wps + o * 9;
            float d = bps[o] + wp[4] * xr[0];
            if (mu_) {
                d += wp[1] * xr[-K];
                if (ml) d += wp[0] * xr[-K - 1];
                if (mr) d += wp[2] * xr[-K + 1];
            }
            if (ml) d += wp[3] * xr[-1];
            if (mr) d += wp[5] * xr[1];
            if (md) {
                d += wp[7] * xr[K];
                if (ml) d += wp[6] * xr[K - 1];
                if (mr) d += wp[8] * xr[K + 1];
            }
            acc[i][jj] = z[bp * 64 + o] * (acc[i][jj] + b2s[o]) + d;
        }
    }
#pragma unroll
    for (int i = 0; i < 8; i++) {
        int o = ty * 8 + i;
        *reinterpret_cast<float4*>(A + (size_t)o * NC + j0) =
            make_float4(acc[i][0], acc[i][1], acc[i][2], acc[i][3]);
    }
}

// ---------------- fold back (gather form, no atomics) ----------------
template<int NW, int K, int S>
__global__ void fold_win(const float* __restrict__ A, float* __restrict__ mix, int woff)
{
    constexpr int W2 = NW * NW, KSQ = K * K;
    constexpr int M = 64 * KSQ;
    constexpr int NC = N_IMG * W2 * KSQ;
    int e = blockIdx.x * 256 + threadIdx.x;
    if (e >= N_IMG * 64 * HW) return;
    int hw = e % HW;
    int t = e / HW;
    int c = t & 63;
    int n = t >> 6;
    int h = hw / HDIM;
    int w = hw - h * HDIM;
    int wi_hi = min(NW - 1, h / S);
    int wi_lo = (h >= K) ? (h - K) / S + 1 : 0;
    int wj_hi = min(NW - 1, w / S);
    int wj_lo = (w >= K) ? (w - K) / S + 1 : 0;
    float sum = 0.f;
    for (int wi = wi_lo; wi <= wi_hi; wi++) {
        int ki = h - wi * S;
        for (int wj = wj_lo; wj <= wj_hi; wj++) {
            int kj = w - wj * S;
            int g = ((c * K + ki) * K + kj) * W2 + wi * NW + wj;
            int q = g / M;
            int mp = g - q * M;
            int o = mp / KSQ;
            int sp = mp - o * KSQ;
            sum += A[(size_t)o * NC + (size_t)(n * W2 + q) * KSQ + sp];
        }
    }
    float cnt = (float)((wi_hi - wi_lo + 1) * (wj_hi - wj_lo + 1));
    mix[((size_t)(n * 192 + woff + c)) * HW + hw] = sum / cnt;
}

// ---------------- host-side per-window driver ----------------
template<int NW, int K, int S, int LPAD, int STRIDE>
static void run_window(const float* xc, const float* w2, const float* b2, const float* wpos,
                       const float* bpos, const float* wse1, const float* wse2,
                       float* Gt, float* A, float* meanU, float* z,
                       float* mix, int woff)
{
    constexpr int W2 = NW * NW, KSQ = K * K;
    constexpr int B = N_IMG * W2;
    constexpr int NC = N_IMG * W2 * KSQ;
    constexpr int wg_smem = (4352 + 64 * STRIDE + 576 + 128) * 4;
    cudaFuncSetAttribute(wgemm_dw<K, NC, LPAD, STRIDE>,
                         cudaFuncAttributeMaxDynamicSharedMemorySize, wg_smem);
    gather_mean<NW, K, S><<<B * 8, 256>>>(xc, Gt, meanU);
    se_kernel<<<B, 64>>>(meanU, w2, b2, wse1, wse2, z);
    wgemm_dw<K, NC, LPAD, STRIDE><<<NC / 128, 256, wg_smem>>>(w2, b2, Gt, wpos, bpos, z, A);
    fold_win<NW, K, S><<<(N_IMG * 64 * HW + 255) / 256, 256>>>(A, mix, woff);
}

extern "C" void kernel_launch(void* const* d_in, const int* in_sizes, int n_in,
                              void* d_out, int out_size)
{
    const float* x    = (const float*)d_in[0];
    const float* w1   = (const float*)d_in[1];
    const float* b1   = (const float*)d_in[2];
    const float* w2   = (const float*)d_in[3];
    const float* b2   = (const float*)d_in[4];
    const float* w3   = (const float*)d_in[5];
    const float* b3   = (const float*)d_in[6];
    const float* wpos = (const float*)d_in[7];
    const float* bpos = (const float*)d_in[8];
    const float* wse1 = (const float*)d_in[9];
    const float* wse2 = (const float*)d_in[10];
    float* out = (float*)d_out;

    float *xc, *Gt, *A, *mix, *meanU, *z;
    cudaGetSymbolAddress((void**)&xc, g_xc);
    cudaGetSymbolAddress((void**)&Gt, g_Gt);
    cudaGetSymbolAddress((void**)&A, g_A);
    cudaGetSymbolAddress((void**)&mix, g_mix);
    cudaGetSymbolAddress((void**)&meanU, g_meanU);
    cudaGetSymbolAddress((void**)&z, g_z);

    constexpr int conv_smem = (192 * 68 + 16 * 264) * 4;   // 69,120 B
    cudaFuncSetAttribute(conv_big<192, 64, false>,
                         cudaFuncAttributeMaxDynamicSharedMemorySize, conv_smem);
    cudaFuncSetAttribute(conv_big<192, 192, true>,
                         cudaFuncAttributeMaxDynamicSharedMemorySize, conv_smem);

    // 1) xc = w1 @ x + b1
    conv_big<192, 64, false><<<dim3(40, 1, 16), 256, conv_smem>>>(w1, b1, x, (const float*)0, xc);

    // 2) windows: (nw, k, s) with per-K halo padding
    run_window<4, 25, 25, 28, 184>(xc, w2, b2, wpos, bpos, wse1, wse2, Gt, A, meanU, z, mix, 0);
    run_window<8, 16, 12, 20, 168>(xc, w2, b2, wpos, bpos, wse1, wse2, Gt, A, meanU, z, mix, 64);
    run_window<12, 12, 8, 16, 160>(xc, w2, b2, wpos, bpos, wse1, wse2, Gt, A, meanU, z, mix, 128);

    // 3) out = w3 @ (mix + x) + b3
    conv_big<192, 192, true><<<dim3(40, 3, 16), 256, conv_smem>>>(w3, b3, mix, x, out);
}

// round 11
// speedup vs baseline: 1.2222x; 1.2222x over previous
#include <cuda_runtime.h>
#include <math.h>

#define N_IMG 16
#define HW 10000
#define HDIM 100

// ---------------- scratch (no allocations allowed) ----------------
__device__ float g_xc[10240000];       // (16,64,100,100)
__device__ float g_G[21233664];        // largest window gather buffer
__device__ float g_A[21233664];        // padded result buffer
__device__ float g_mix[30720000];      // (16,192,100,100) folded concat
__device__ float g_meanU[147456];      // B*64 (B<=2304)
__device__ float g_z[147456];          // SE scales

// ---------------- big 1x1 conv: 64m x 256p tile, 8x8 thread tile, plain float ----
// Y[n,m,p] = sum_k W[m,k] * (X0[n,k,p] (+ X1[n,k,p])) + bias[m]
template<int KDIM, int MOUT, bool ADDX>
__global__ __launch_bounds__(256, 2) void conv_big(
    const float* __restrict__ Wm, const float* __restrict__ bias,
    const float* __restrict__ X0, const float* __restrict__ X1,
    float* __restrict__ Y)
{
    extern __shared__ float sm[];
    float* Ws = sm;                  // [KDIM][68] transposed (k rows, m inner)
    float* Xs = sm + KDIM * 68;      // [16][264]
    const int tid = threadIdx.x;
    const int tx = tid & 31;         // p group (8 cols each)
    const int ty = tid >> 5;         // m group (8 rows each)
    const int p0 = blockIdx.x * 256;
    const int m0 = blockIdx.y * 64;
    const int n  = blockIdx.z;
    const float* Xb0 = X0 + (size_t)n * KDIM * HW;
    const float* Xb1 = X1 ? (X1 + (size_t)n * KDIM * HW) : (const float*)0;

    for (int idx = tid; idx < 64 * KDIM; idx += 256) {
        int mm = idx / KDIM;
        int kc = idx - mm * KDIM;
        Ws[kc * 68 + mm] = Wm[(m0 + mm) * KDIM + kc];
    }

    float acc[8][8];
#pragma unroll
    for (int i = 0; i < 8; i++)
#pragma unroll
        for (int j = 0; j < 8; j++) acc[i][j] = 0.f;

    for (int k0 = 0; k0 < KDIM; k0 += 16) {
        __syncthreads();
#pragma unroll
        for (int idx = tid; idx < 4096; idx += 256) {
            int kk = idx >> 8;
            int pp = idx & 255;
            int p = p0 + pp;
            float v = 0.f;
            if (p < HW) {
                v = Xb0[(size_t)(k0 + kk) * HW + p];
                if (ADDX) v += Xb1[(size_t)(k0 + kk) * HW + p];
            }
            Xs[kk * 264 + pp] = v;
        }
        __syncthreads();
#pragma unroll 4
        for (int kk = 0; kk < 16; kk++) {
            const float4 wa = *reinterpret_cast<const float4*>(Ws + (k0 + kk) * 68 + ty * 8);
            const float4 wb = *reinterpret_cast<const float4*>(Ws + (k0 + kk) * 68 + ty * 8 + 4);
            const float4 xa = *reinterpret_cast<const float4*>(Xs + kk * 264 + tx * 8);
            const float4 xb = *reinterpret_cast<const float4*>(Xs + kk * 264 + tx * 8 + 4);
            float wv[8] = {wa.x, wa.y, wa.z, wa.w, wb.x, wb.y, wb.z, wb.w};
            float xv[8] = {xa.x, xa.y, xa.z, xa.w, xb.x, xb.y, xb.z, xb.w};
#pragma unroll
            for (int i = 0; i < 8; i++)
#pragma unroll
                for (int j = 0; j < 8; j++)
                    acc[i][j] += wv[i] * xv[j];
        }
    }

    int p = p0 + tx * 8;
    if (p < HW) {                    // HW % 8 == 0 -> covers p..p+7
#pragma unroll
        for (int i = 0; i < 8; i++) {
            int m = m0 + ty * 8 + i;
            float bv = bias[m];
            float* yp = Y + (size_t)(n * MOUT + m) * HW + p;
            *reinterpret_cast<float4*>(yp) =
                make_float4(acc[i][0] + bv, acc[i][1] + bv, acc[i][2] + bv, acc[i][3] + bv);
            *reinterpret_cast<float4*>(yp + 4) =
                make_float4(acc[i][4] + bv, acc[i][5] + bv, acc[i][6] + bv, acc[i][7] + bv);
        }
    }
}

// ---------------- gather: xc -> G in u3 flat order (n, m, w) ----------------
template<int NW, int K, int S>
__global__ void gather_win(const float* __restrict__ xc, float* __restrict__ G)
{
    constexpr int W2 = NW * NW;
    constexpr int KSQ = K * K;
    constexpr int M = 64 * KSQ;
    constexpr int PER_N = M * W2;
    int e = blockIdx.x * 256 + threadIdx.x;
    if (e >= N_IMG * PER_N) return;
    int n = e / PER_N;
    int r = e - n * PER_N;
    int m = r / W2;
    int w = r - m * W2;
    int wi = w / NW, wj = w - wi * NW;
    int c = m / KSQ;
    int rem = m - c * KSQ;
    int ki = rem / K, kj = rem - ki * K;
    int h = wi * S + ki, wc = wj * S + kj;
    G[e] = xc[((n * 64 + c) * HDIM + h) * HDIM + wc];
}

// ---------------- per-(b,c) spatial mean of U ----------------
template<int K>
__global__ void mean_u(const float* __restrict__ G, float* __restrict__ meanU, int rows)
{
    constexpr int KSQ = K * K;
    int gw = (blockIdx.x * 256 + threadIdx.x) >> 5;
    int lane = threadIdx.x & 31;
    if (gw >= rows) return;
    const float* p = G + (size_t)gw * KSQ;
    float s = 0.f;
    for (int i = lane; i < KSQ; i += 32) s += p[i];
#pragma unroll
    for (int off = 16; off; off >>= 1) s += __shfl_down_sync(0xffffffffu, s, off);
    if (lane == 0) meanU[gw] = s * (1.0f / KSQ);
}

// ---------------- SE head (tiny) ----------------
__global__ void se_kernel(const float* __restrict__ meanU, const float* __restrict__ w2,
                          const float* __restrict__ b2, const float* __restrict__ wse1,
                          const float* __restrict__ wse2, float* __restrict__ z)
{
    __shared__ float mu[64], my[64], hb[4];
    int b = blockIdx.x, t = threadIdx.x;
    mu[t] = meanU[b * 64 + t];
    __syncthreads();
    float acc = b2[t];
#pragma unroll 8
    for (int c = 0; c < 64; c++) acc += w2[t * 64 + c] * mu[c];
    my[t] = acc;
    __syncthreads();
    if (t < 4) {
        float h = 0.f;
#pragma unroll 8
        for (int o = 0; o < 64; o++) h += wse1[t * 64 + o] * my[o];
        hb[t] = fmaxf(h, 0.f);
    }
    __syncthreads();
    float za = 0.f;
#pragma unroll
    for (int j = 0; j < 4; j++) za += wse2[t * 4 + j] * hb[j];
    z[b * 64 + t] = 1.f / (1.f + expf(-za));
}

// ---------------- fused: 64x64 conv1x1 (scaled by SE z) + dwconv3x3 ----------------
// One block per patch b; whole patch (64 x k^2) resident in smem. (R2-identical)
template<int NW, int K, int S>
__global__ __launch_bounds__(256) void win_compute(
    const float* __restrict__ G, const float* __restrict__ w2, const float* __restrict__ b2,
    const float* __restrict__ wpos, const float* __restrict__ bpos, const float* __restrict__ z,
    float* __restrict__ A)
{
    constexpr int KSQ = K * K;
    constexpr int KSQ4 = (KSQ + 3) & ~3;
    constexpr int M = 64 * KSQ;
    constexpr int M4 = 64 * KSQ4;
    constexpr int NSG = KSQ4 / 4;
    extern __shared__ float sm[];
    float* Us  = sm;                 // 64*KSQ4, [c][sp] padded
    float* w2t = Us + 64 * KSQ4;     // 4096, [c][o]
    float* wps = w2t + 4096;         // 576
    float* zb  = wps + 576;          // 64
    float* b2s = zb + 64;            // 64
    float* bps = b2s + 64;           // 64
    const int b = blockIdx.x;
    const int tid = threadIdx.x;
    const size_t gin  = (size_t)b * M;
    const size_t gout = (size_t)b * M4;

    for (int idx = tid; idx < 64 * KSQ4; idx += 256) {
        int c = idx / KSQ4;
        int sp = idx - c * KSQ4;
        Us[idx] = (sp < KSQ) ? G[gin + c * KSQ + sp] : 0.f;
    }
    for (int idx = tid; idx < 4096; idx += 256) {
        int c = idx >> 6, o = idx & 63;
        w2t[idx] = w2[o * 64 + c];
    }
    for (int idx = tid; idx < 576; idx += 256) wps[idx] = wpos[idx];
    if (tid < 64) { zb[tid] = z[b * 64 + tid]; b2s[tid] = b2[tid]; bps[tid] = bpos[tid]; }
    __syncthreads();

    const int og = tid >> 4;     // 16 groups of 4 out channels
    const int sg0 = tid & 15;    // spatial float4 group start
    const float4* Us4  = reinterpret_cast<const float4*>(Us);
    const float4* w2t4 = reinterpret_cast<const float4*>(w2t);

    for (int sg = sg0; sg < NSG; sg += 16) {
        float acc[4][4];
#pragma unroll
        for (int i = 0; i < 4; i++) { acc[i][0] = 0.f; acc[i][1] = 0.f; acc[i][2] = 0.f; acc[i][3] = 0.f; }
#pragma unroll 8
        for (int c = 0; c < 64; c++) {
            float4 u  = Us4[c * NSG + sg];
            float4 wv = w2t4[c * 16 + og];
            acc[0][0] += wv.x * u.x; acc[0][1] += wv.x * u.y; acc[0][2] += wv.x * u.z; acc[0][3] += wv.x * u.w;
            acc[1][0] += wv.y * u.x; acc[1][1] += wv.y * u.y; acc[1][2] += wv.y * u.z; acc[1][3] += wv.y * u.w;
            acc[2][0] += wv.z * u.x; acc[2][1] += wv.z * u.y; acc[2][2] += wv.z * u.z; acc[2][3] += wv.z * u.w;
            acc[3][0] += wv.w * u.x; acc[3][1] += wv.w * u.y; acc[3][2] += wv.w * u.z; acc[3][3] += wv.w * u.w;
        }
        const int sp0 = sg * 4;
#pragma unroll
        for (int oo = 0; oo < 4; oo++) {
            int o = og * 4 + oo;
            const float* urow = Us + o * KSQ4;
            const float* wp = wps + o * 9;
            float zo = zb[o], b2o = b2s[o], bpo = bps[o];
            float outv[4];
#pragma unroll
            for (int ss = 0; ss < 4; ss++) {
                int sp = sp0 + ss;
                float val = 0.f;
                if (sp < KSQ) {
                    int i = sp / K;
                    int j = sp - i * K;
                    float d = bpo;
#pragma unroll
                    for (int di = -1; di <= 1; di++) {
                        int ii = i + di;
                        if (ii >= 0 && ii < K) {
#pragma unroll
                            for (int dj = -1; dj <= 1; dj++) {
                                int jj = j + dj;
                                if (jj >= 0 && jj < K)
                                    d += wp[(di + 1) * 3 + (dj + 1)] * urow[ii * K + jj];
                            }
                        }
                    }
                    val = zo * (acc[oo][ss] + b2o) + d;
                }
                outv[ss] = val;
            }
            *reinterpret_cast<float4*>(A + gout + o * KSQ4 + sp0) =
                make_float4(outv[0], outv[1], outv[2], outv[3]);
        }
    }
}

// ---------------- fold back (gather form, no atomics) ----------------
template<int NW, int K, int S>
__global__ void fold_win(const float* __restrict__ A, float* __restrict__ mix, int woff)
{
    constexpr int W2 = NW * NW, KSQ = K * K, KSQ4 = (KSQ + 3) & ~3;
    constexpr int M = 64 * KSQ, M4 = 64 * KSQ4;
    int e = blockIdx.x * 256 + threadIdx.x;
    if (e >= N_IMG * 64 * HW) return;
    int hw = e % HW;
    int t = e / HW;
    int c = t & 63;
    int n = t >> 6;
    int h = hw / HDIM;
    int w = hw - h * HDIM;
    int wi_hi = min(NW - 1, h / S);
    int wi_lo = (h >= K) ? (h - K) / S + 1 : 0;
    int wj_hi = min(NW - 1, w / S);
    int wj_lo = (w >= K) ? (w - K) / S + 1 : 0;
    const float* An = A + (size_t)n * W2 * M4;
    float sum = 0.f;
    for (int wi = wi_lo; wi <= wi_hi; wi++) {
        int ki = h - wi * S;
        for (int wj = wj_lo; wj <= wj_hi; wj++) {
            int kj = w - wj * S;
            int g = ((c * K + ki) * K + kj) * W2 + wi * NW + wj;
            int q = g / M;
            int mp = g - q * M;
            int o = mp / KSQ;
            int sp = mp - o * KSQ;
            sum += An[(size_t)q * M4 + o * KSQ4 + sp];
        }
    }
    float cnt = (float)((wi_hi - wi_lo + 1) * (wj_hi - wj_lo + 1));
    mix[((size_t)(n * 192 + woff + c)) * HW + hw] = sum / cnt;
}

// ---------------- host-side per-window driver ----------------
template<int NW, int K, int S>
static void run_window(const float* xc, const float* w2, const float* b2, const float* wpos,
                       const float* bpos, const float* wse1, const float* wse2,
                       float* G, float* A, float* meanU, float* z, float* mix, int woff)
{
    constexpr int W2 = NW * NW, KSQ = K * K, KSQ4 = (KSQ + 3) & ~3;
    constexpr int M = 64 * KSQ;
    constexpr int B = N_IMG * W2;
    constexpr int total = N_IMG * M * W2;
    constexpr int smem = (64 * KSQ4 + 4096 + 576 + 192) * 4;
    cudaFuncSetAttribute(win_compute<NW, K, S>, cudaFuncAttributeMaxDynamicSharedMemorySize, smem);
    gather_win<NW, K, S><<<(total + 255) / 256, 256>>>(xc, G);
    mean_u<K><<<(B * 64 + 7) / 8, 256>>>(G, meanU, B * 64);
    se_kernel<<<B, 64>>>(meanU, w2, b2, wse1, wse2, z);
    win_compute<NW, K, S><<<B, 256, smem>>>(G, w2, b2, wpos, bpos, z, A);
    fold_win<NW, K, S><<<(N_IMG * 64 * HW + 255) / 256, 256>>>(A, mix, woff);
}

extern "C" void kernel_launch(void* const* d_in, const int* in_sizes, int n_in,
                              void* d_out, int out_size)
{
    const float* x    = (const float*)d_in[0];
    const float* w1   = (const float*)d_in[1];
    const float* b1   = (const float*)d_in[2];
    const float* w2   = (const float*)d_in[3];
    const float* b2   = (const float*)d_in[4];
    const float* w3   = (const float*)d_in[5];
    const float* b3   = (const float*)d_in[6];
    const float* wpos = (const float*)d_in[7];
    const float* bpos = (const float*)d_in[8];
    const float* wse1 = (const float*)d_in[9];
    const float* wse2 = (const float*)d_in[10];
    float* out = (float*)d_out;

    float *xc, *G, *A, *mix, *meanU, *z;
    cudaGetSymbolAddress((void**)&xc, g_xc);
    cudaGetSymbolAddress((void**)&G, g_G);
    cudaGetSymbolAddress((void**)&A, g_A);
    cudaGetSymbolAddress((void**)&mix, g_mix);
    cudaGetSymbolAddress((void**)&meanU, g_meanU);
    cudaGetSymbolAddress((void**)&z, g_z);

    constexpr int conv_smem = (192 * 68 + 16 * 264) * 4;   // 69,120 B
    cudaFuncSetAttribute(conv_big<192, 64, false>,
                         cudaFuncAttributeMaxDynamicSharedMemorySize, conv_smem);
    cudaFuncSetAttribute(conv_big<192, 192, true>,
                         cudaFuncAttributeMaxDynamicSharedMemorySize, conv_smem);

    // 1) xc = w1 @ x + b1
    conv_big<192, 64, false><<<dim3(40, 1, 16), 256, conv_smem>>>(w1, b1, x, (const float*)0, xc);

    // 2) windows: (nw, k, s)
    run_window<4, 25, 25>(xc, w2, b2, wpos, bpos, wse1, wse2, G, A, meanU, z, mix, 0);
    run_window<8, 16, 12>(xc, w2, b2, wpos, bpos, wse1, wse2, G, A, meanU, z, mix, 64);
    run_window<12, 12, 8>(xc, w2, b2, wpos, bpos, wse1, wse2, G, A, meanU, z, mix, 128);

    // 3) out = w3 @ (mix + x) + b3
    conv_big<192, 192, true><<<dim3(40, 3, 16), 256, conv_smem>>>(w3, b3, mix, x, out);
}